// round 1
// baseline (speedup 1.0000x reference)
#include <cuda_runtime.h>

// Bloch-vector rotations matching RX/RY/RZ = exp(-i t sigma/2) conjugation.
__device__ __forceinline__ void rotX(float t, float& x, float& y, float& z){
    float s, c; sincosf(t, &s, &c);
    float ny = c*y - s*z, nz = s*y + c*z; y = ny; z = nz; (void)x;
}
__device__ __forceinline__ void rotY(float t, float& x, float& y, float& z){
    float s, c; sincosf(t, &s, &c);
    float nx = c*x + s*z, nz = -s*x + c*z; x = nx; z = nz;
}
__device__ __forceinline__ void rotZ(float t, float& x, float& y, float& z){
    float s, c; sincosf(t, &s, &c);
    float nx = c*x - s*y, ny = s*x + c*y; x = nx; y = ny;
}

__device__ __forceinline__ float wred(float v){
    #pragma unroll
    for (int o = 16; o; o >>= 1) v += __shfl_xor_sync(0xffffffffu, v, o);
    return v;
}

// CNOT(c,t) Pauli conjugation table, index = pc*4 + pt (0=I,1=X,2=Y,3=Z).
// entry = newc | newt<<2 | signbit<<4
//   (I,I)+ (I,X)+ (I,Y)->(Z,Y)+ (I,Z)->(Z,Z)+
//   (X,I)->(X,X)+ (X,X)->(X,I)+ (X,Y)->(Y,Z)+ (X,Z)->(Y,Y)-
//   (Y,I)->(Y,X)+ (Y,X)->(Y,I)+ (Y,Y)->(X,Z)- (Y,Z)->(X,Y)+
//   (Z,I)+ (Z,X)+ (Z,Y)->(I,Y)+ (Z,Z)->(I,Z)+
__constant__ unsigned char CONJ[16] = {
    0, 4, 11, 15,
    5, 1, 14, 26,
    6, 2, 29, 9,
    3, 7, 8, 12
};

__global__ void __launch_bounds__(256)
qie_kernel(const float* __restrict__ x,      // [8,16,4,3]
           const float* __restrict__ posw,   // [16,2]
           const float* __restrict__ l1w,    // [20,3]
           const float* __restrict__ l2w,    // [16,3]
           const float* __restrict__ hw,     // [512,4]
           const float* __restrict__ hb,     // [512]
           float* __restrict__ out)          // [8,512]
{
    __shared__ float M[4][20][4];   // [block][qubit][pauli]; [..][0] = <I> = 1
    __shared__ float Nv[16][3];     // Bloch rows of O_q
    __shared__ float acc[8][8];     // per-warp partials for 7 accumulators
    __shared__ float qsh[4];
    __shared__ float nwarp[8];
    __shared__ float ntot;

    const int b = blockIdx.x;
    const int t = threadIdx.x;

    // ---- per-qubit Bloch vectors (80 threads) + observable Bloch rows (16 threads)
    if (t < 80) {
        int qb = t / 20, i = t % 20;
        int p = 4*qb + i/5, j = i % 5;
        float vx = 0.f, vy = 0.f, vz = 1.f;
        if (j < 4) {
            const float* xp = x + (((size_t)b*16 + p)*4 + j)*3;
            rotX(xp[0], vx, vy, vz); rotY(xp[1], vx, vy, vz); rotZ(xp[2], vx, vy, vz);
        } else {
            rotX(posw[2*p], vx, vy, vz); rotY(posw[2*p+1], vx, vy, vz);
        }
        rotX(l1w[3*i], vx, vy, vz); rotY(l1w[3*i+1], vx, vy, vz); rotZ(l1w[3*i+2], vx, vy, vz);
        M[qb][i][0] = 1.f; M[qb][i][1] = vx; M[qb][i][2] = vy; M[qb][i][3] = vz;
    } else if (t < 96) {
        int q = t - 80;
        float a = l2w[3*q], be = l2w[3*q+1];
        float sa, ca, sb, cb;
        sincosf(a, &sa, &ca); sincosf(be, &sb, &cb);
        // O_q = U^dag Z U with U = RZ RY RX  ->  n = (-sin b, sin a cos b, cos a cos b)
        Nv[q][0] = -sb; Nv[q][1] = sa*cb; Nv[q][2] = ca*cb;
    }
    __syncthreads();

    // ---- thread t owns initial Pauli pattern (a0,a1,a2,a3) = base-4 digits of t,
    //      which is exactly the 2-bit-packed string on qubits 0..3.
    const int a0 = t & 3, a1 = (t >> 2) & 3, a2 = (t >> 4) & 3, a3 = (t >> 6) & 3;
    unsigned long long s = (unsigned long long)t;  // qubits 4..19 = I
    int sign = 0;
    // psi = C19...C0 |prod>  =>  conjugate by C19 first, C0 last.
    #pragma unroll
    for (int i = 19; i >= 0; --i) {
        const int c = i, tt = (i + 1) % 20;
        int pc = (int)((s >> (2*c)) & 3ull);
        int pt = (int)((s >> (2*tt)) & 3ull);
        int e = CONJ[pc*4 + pt];
        s &= ~((3ull << (2*c)) | (3ull << (2*tt)));
        s |= ((unsigned long long)(e & 3)) << (2*c);
        s |= ((unsigned long long)((e >> 2) & 3)) << (2*tt);
        sign ^= (e >> 4);
    }
    const float sgn = sign ? -1.f : 1.f;

    // <psi_qb | P(a) | psi_qb> for each of the 4 blocks
    float val[4];
    #pragma unroll
    for (int qb = 0; qb < 4; ++qb) {
        float pr = sgn;
        #pragma unroll
        for (int i = 0; i < 20; ++i)
            pr *= M[qb][i][(int)((s >> (2*i)) & 3ull)];
        val[qb] = pr;
    }

    // ---- accumulate the 7 expectations
    // [0..3] Efull[qb]; [4] e123 (psis[0], wires 1,2,3); [5] e01; [6] e012
    float part[7] = {0,0,0,0,0,0,0};
    const bool f0 = a0 > 0, f1 = a1 > 0, f2 = a2 > 0, f3 = a3 > 0;
    if (f0 && f1 && f2 && f3) {
        #pragma unroll
        for (int qb = 0; qb < 4; ++qb)
            part[qb] = Nv[4*qb+0][a0-1] * Nv[4*qb+1][a1-1] *
                       Nv[4*qb+2][a2-1] * Nv[4*qb+3][a3-1] * val[qb];
    }
    if (!f0 && f1 && f2 && f3)
        part[4] = Nv[1][a1-1] * Nv[2][a2-1] * Nv[3][a3-1] * val[0];
    if (f0 && f1 && !f2 && !f3)
        part[5] = Nv[0][a0-1] * Nv[1][a1-1] * val[0];
    if (f0 && f1 && f2 && !f3)
        part[6] = Nv[0][a0-1] * Nv[1][a1-1] * Nv[2][a2-1] * val[0];

    const int warp = t >> 5, lane = t & 31;
    #pragma unroll
    for (int k = 0; k < 7; ++k) {
        float r = wred(part[k]);
        if (lane == 0) acc[warp][k] = r;
    }
    __syncthreads();

    if (t == 0) {
        float E[7];
        #pragma unroll
        for (int k = 0; k < 7; ++k) {
            float v = 0.f;
            #pragma unroll
            for (int w = 0; w < 8; ++w) v += acc[w][k];   // fixed order: deterministic
            E[k] = v;
        }
        qsh[0] = E[4] * E[1] * E[2] * E[3];  // e0
        qsh[1] = E[5];                       // e1
        qsh[2] = E[6];                       // e2
        qsh[3] = E[0];                       // e3
    }
    __syncthreads();

    // ---- head: y = q @ W^T + b, then L2 normalize; 2 outputs per thread
    const float q0 = qsh[0], q1 = qsh[1], q2 = qsh[2], q3 = qsh[3];
    const int k0 = t, k1 = t + 256;
    float y0 = hb[k0] + q0*hw[k0*4+0] + q1*hw[k0*4+1] + q2*hw[k0*4+2] + q3*hw[k0*4+3];
    float y1 = hb[k1] + q0*hw[k1*4+0] + q1*hw[k1*4+1] + q2*hw[k1*4+2] + q3*hw[k1*4+3];
    float ssum = wred(y0*y0 + y1*y1);
    if (lane == 0) nwarp[warp] = ssum;
    __syncthreads();
    if (t == 0) {
        float v = 0.f;
        #pragma unroll
        for (int w = 0; w < 8; ++w) v += nwarp[w];
        ntot = v;
    }
    __syncthreads();
    const float d = fmaxf(sqrtf(ntot), 1e-12f);
    out[(size_t)b*512 + k0] = y0 / d;
    out[(size_t)b*512 + k1] = y1 / d;
}

extern "C" void kernel_launch(void* const* d_in, const int* in_sizes, int n_in,
                              void* d_out, int out_size)
{
    // Map inputs by (unique) element counts, robust to ordering:
    // x=1536, pos_weights=32, layer_1_weights=60, layer_2_weights=48,
    // head_w=2048, head_b=512
    const float *x = nullptr, *pw = nullptr, *l1 = nullptr,
                *l2 = nullptr, *hw = nullptr, *hb = nullptr;
    for (int i = 0; i < n_in; ++i) {
        const float* p = (const float*)d_in[i];
        switch (in_sizes[i]) {
            case 1536: x  = p; break;
            case 32:   pw = p; break;
            case 60:   l1 = p; break;
            case 48:   l2 = p; break;
            case 2048: hw = p; break;
            case 512:  hb = p; break;
            default: break;
        }
    }
    qie_kernel<<<8, 256>>>(x, pw, l1, l2, hw, hb, (float*)d_out);
}

// round 2
// speedup vs baseline: 1.0389x; 1.0389x over previous
#include <cuda_runtime.h>

// Bloch-vector rotations matching RX/RY/RZ = exp(-i t sigma/2) conjugation.
// __sincosf: fast MUFU path; |angle| <= ~5 here, abs err ~1e-6, budget 1e-3.
__device__ __forceinline__ void rotX(float t, float& x, float& y, float& z){
    float s, c; __sincosf(t, &s, &c);
    float ny = c*y - s*z, nz = s*y + c*z; y = ny; z = nz; (void)x;
}
__device__ __forceinline__ void rotY(float t, float& x, float& y, float& z){
    float s, c; __sincosf(t, &s, &c);
    float nx = c*x + s*z, nz = -s*x + c*z; x = nx; z = nz;
}
__device__ __forceinline__ void rotZ(float t, float& x, float& y, float& z){
    float s, c; __sincosf(t, &s, &c);
    float nx = c*x - s*y, ny = s*x + c*y; x = nx; y = ny;
}

__device__ __forceinline__ float wred(float v){
    #pragma unroll
    for (int o = 16; o; o >>= 1) v += __shfl_xor_sync(0xffffffffu, v, o);
    return v;
}

// CNOT(c,t) Pauli conjugation table, index = pc*4 + pt (0=I,1=X,2=Y,3=Z).
// entry = newc | newt<<2 | signbit<<4
__constant__ unsigned char CONJ[16] = {
    0, 4, 11, 15,
    5, 1, 14, 26,
    6, 2, 29, 9,
    3, 7, 8, 12
};

__global__ void __launch_bounds__(256)
qie_kernel(const float* __restrict__ x,      // [8,16,4,3]
           const float* __restrict__ posw,   // [16,2]
           const float* __restrict__ l1w,    // [20,3]
           const float* __restrict__ l2w,    // [16,3]
           const float* __restrict__ hw,     // [512,4]
           const float* __restrict__ hb,     // [512]
           float* __restrict__ out)          // [8,512]
{
    __shared__ float M[20][4][4];   // [qubit][pauli][block]; [..][0][..] = <I> = 1
    __shared__ float Nv[16][3];     // Bloch rows of O_q
    __shared__ float acc[8][8];     // per-warp partials for 7 accumulators
    __shared__ float Esh[8];
    __shared__ float nwarp[8];

    const int b = blockIdx.x;
    const int t = threadIdx.x;
    const int warp = t >> 5, lane = t & 31;

    // ---- prefetch head GEMV operands (independent of everything; hides L2/DRAM lat)
    const int k0 = t, k1 = t + 256;
    const float4 w0 = ((const float4*)hw)[k0];
    const float4 w1 = ((const float4*)hw)[k1];
    const float b0 = hb[k0], b1 = hb[k1];

    // ---- per-qubit Bloch vectors (80 threads) + observable Bloch rows (16 threads)
    if (t < 80) {
        int qb = t / 20, i = t % 20;
        int p = 4*qb + i/5, j = i % 5;
        float vx = 0.f, vy = 0.f, vz = 1.f;
        if (j < 4) {
            const float* xp = x + (((size_t)b*16 + p)*4 + j)*3;
            rotX(xp[0], vx, vy, vz); rotY(xp[1], vx, vy, vz); rotZ(xp[2], vx, vy, vz);
        } else {
            rotX(posw[2*p], vx, vy, vz); rotY(posw[2*p+1], vx, vy, vz);
        }
        rotX(l1w[3*i], vx, vy, vz); rotY(l1w[3*i+1], vx, vy, vz); rotZ(l1w[3*i+2], vx, vy, vz);
        M[i][0][qb] = 1.f; M[i][1][qb] = vx; M[i][2][qb] = vy; M[i][3][qb] = vz;
    } else if (t < 96) {
        int q = t - 80;
        float sa, ca, sb, cb;
        __sincosf(l2w[3*q],   &sa, &ca);
        __sincosf(l2w[3*q+1], &sb, &cb);
        // O_q = U^dag Z U with U = RZ RY RX  ->  n = (-sin b, sin a cos b, cos a cos b)
        Nv[q][0] = -sb; Nv[q][1] = sa*cb; Nv[q][2] = ca*cb;
    }

    // ---- Clifford pullback of pattern t through the 20-CNOT ring (no shared deps)
    const int a0 = t & 3, a1 = (t >> 2) & 3, a2 = (t >> 4) & 3, a3 = (t >> 6) & 3;
    unsigned long long s = (unsigned long long)t;  // qubits 4..19 = I
    int sign = 0;
    #pragma unroll
    for (int i = 19; i >= 0; --i) {
        const int c = i, tt = (i + 1) % 20;
        int pc = (int)((s >> (2*c)) & 3ull);
        int pt = (int)((s >> (2*tt)) & 3ull);
        int e = CONJ[pc*4 + pt];
        s &= ~((3ull << (2*c)) | (3ull << (2*tt)));
        s |= ((unsigned long long)(e & 3)) << (2*c);
        s |= ((unsigned long long)((e >> 2) & 3)) << (2*tt);
        sign ^= (e >> 4);
    }
    const float sgn = sign ? -1.f : 1.f;

    __syncthreads();

    // ---- <psi_qb | P(a) | psi_qb> for all 4 blocks: one LDS.128 per qubit
    float v0 = sgn, v1 = sgn, v2 = sgn, v3 = sgn;
    #pragma unroll
    for (int i = 0; i < 20; ++i) {
        int p = (int)((s >> (2*i)) & 3ull);
        float4 f = *(const float4*)&M[i][p][0];
        v0 *= f.x; v1 *= f.y; v2 *= f.z; v3 *= f.w;
    }

    // ---- 7 expectations: [0..3] Efull[qb]; [4] e123; [5] e01; [6] e012
    float part[7] = {0,0,0,0,0,0,0};
    const bool f0 = a0 > 0, f1 = a1 > 0, f2 = a2 > 0, f3 = a3 > 0;
    if (f0 && f1 && f2 && f3) {
        part[0] = Nv[0][a0-1]  * Nv[1][a1-1]  * Nv[2][a2-1]  * Nv[3][a3-1]  * v0;
        part[1] = Nv[4][a0-1]  * Nv[5][a1-1]  * Nv[6][a2-1]  * Nv[7][a3-1]  * v1;
        part[2] = Nv[8][a0-1]  * Nv[9][a1-1]  * Nv[10][a2-1] * Nv[11][a3-1] * v2;
        part[3] = Nv[12][a0-1] * Nv[13][a1-1] * Nv[14][a2-1] * Nv[15][a3-1] * v3;
    }
    if (!f0 && f1 && f2 && f3)
        part[4] = Nv[1][a1-1] * Nv[2][a2-1] * Nv[3][a3-1] * v0;
    if (f0 && f1 && !f2 && !f3)
        part[5] = Nv[0][a0-1] * Nv[1][a1-1] * v0;
    if (f0 && f1 && f2 && !f3)
        part[6] = Nv[0][a0-1] * Nv[1][a1-1] * Nv[2][a2-1] * v0;

    #pragma unroll
    for (int k = 0; k < 7; ++k) {
        float r = wred(part[k]);
        if (lane == 0) acc[warp][k] = r;
    }
    __syncthreads();

    // Parallel final combine: threads 0..6 sum the 8 warp partials (fixed order).
    if (t < 7) {
        float v = 0.f;
        #pragma unroll
        for (int w = 0; w < 8; ++w) v += acc[w][t];
        Esh[t] = v;
    }
    __syncthreads();

    // All threads form q redundantly (3 FMULs) — no serial section, no extra barrier.
    const float q0 = Esh[4] * Esh[1] * Esh[2] * Esh[3];  // e0
    const float q1 = Esh[5];                             // e1
    const float q2 = Esh[6];                             // e2
    const float q3 = Esh[0];                             // e3

    // ---- head: y = q @ W^T + b, then L2 normalize; 2 outputs per thread
    float y0 = b0 + q0*w0.x + q1*w0.y + q2*w0.z + q3*w0.w;
    float y1 = b1 + q0*w1.x + q1*w1.y + q2*w1.z + q3*w1.w;
    float ssum = wred(y0*y0 + y1*y1);
    if (lane == 0) nwarp[warp] = ssum;
    __syncthreads();

    float n = 0.f;
    #pragma unroll
    for (int w = 0; w < 8; ++w) n += nwarp[w];           // fixed order, all threads
    const float d = fmaxf(sqrtf(n), 1e-12f);
    const float r = 1.0f / d;
    out[(size_t)b*512 + k0] = y0 * r;
    out[(size_t)b*512 + k1] = y1 * r;
}

extern "C" void kernel_launch(void* const* d_in, const int* in_sizes, int n_in,
                              void* d_out, int out_size)
{
    // Map inputs by unique element counts:
    // x=1536, pos_weights=32, layer_1_weights=60, layer_2_weights=48,
    // head_w=2048, head_b=512
    const float *x = nullptr, *pw = nullptr, *l1 = nullptr,
                *l2 = nullptr, *hw = nullptr, *hb = nullptr;
    for (int i = 0; i < n_in; ++i) {
        const float* p = (const float*)d_in[i];
        switch (in_sizes[i]) {
            case 1536: x  = p; break;
            case 32:   pw = p; break;
            case 60:   l1 = p; break;
            case 48:   l2 = p; break;
            case 2048: hw = p; break;
            case 512:  hb = p; break;
            default: break;
        }
    }
    qie_kernel<<<8, 256>>>(x, pw, l1, l2, hw, hb, (float*)d_out);
}

// round 3
// speedup vs baseline: 1.3024x; 1.2537x over previous
#include <cuda_runtime.h>

// Bloch-vector rotations matching RX/RY/RZ = exp(-i t sigma/2) conjugation.
__device__ __forceinline__ void rotX(float t, float& x, float& y, float& z){
    float s, c; __sincosf(t, &s, &c);
    float ny = c*y - s*z, nz = s*y + c*z; y = ny; z = nz; (void)x;
}
__device__ __forceinline__ void rotY(float t, float& x, float& y, float& z){
    float s, c; __sincosf(t, &s, &c);
    float nx = c*x + s*z, nz = -s*x + c*z; x = nx; z = nz;
}
__device__ __forceinline__ void rotZ(float t, float& x, float& y, float& z){
    float s, c; __sincosf(t, &s, &c);
    float nx = c*x - s*y, ny = s*x + c*y; x = nx; y = ny;
}

__device__ __forceinline__ float wred(float v){
    #pragma unroll
    for (int o = 16; o; o >>= 1) v += __shfl_xor_sync(0xffffffffu, v, o);
    return v;
}

__global__ void __launch_bounds__(256)
qie_kernel(const float* __restrict__ x,      // [8,16,4,3]
           const float* __restrict__ posw,   // [16,2]
           const float* __restrict__ l1w,    // [20,3]
           const float* __restrict__ l2w,    // [16,3]
           const float* __restrict__ hw,     // [512,4]
           const float* __restrict__ hb,     // [512]
           float* __restrict__ out)          // [8,512]
{
    // M layout: [qubit][sympl pauli][block], sympl index = x | z<<1:
    //   0=I (always 1), 1=X, 2=Z, 3=Y
    __shared__ float M[20][4][4];
    __shared__ float Nv[16][3];     // Bloch rows of O_q  (X,Y,Z order)
    __shared__ float acc[8][8];     // per-warp partials for 7 accumulators
    __shared__ float Esh[8];
    __shared__ float nwarp[8];

    const int b = blockIdx.x;
    const int t = threadIdx.x;
    const int warp = t >> 5, lane = t & 31;

    // ---- prefetch head GEMV operands (independent; hides L2/DRAM latency)
    const int k0 = t, k1 = t + 256;
    const float4 w0 = ((const float4*)hw)[k0];
    const float4 w1 = ((const float4*)hw)[k1];
    const float b0 = hb[k0], b1 = hb[k1];

    // ---- per-qubit Bloch vectors (80 threads) + observable Bloch rows (16 threads)
    if (t < 80) {
        int qb = t / 20, i = t % 20;
        int p = 4*qb + i/5, j = i % 5;
        float vx = 0.f, vy = 0.f, vz = 1.f;
        if (j < 4) {
            const float* xp = x + (((size_t)b*16 + p)*4 + j)*3;
            rotX(xp[0], vx, vy, vz); rotY(xp[1], vx, vy, vz); rotZ(xp[2], vx, vy, vz);
        } else {
            rotX(posw[2*p], vx, vy, vz); rotY(posw[2*p+1], vx, vy, vz);
        }
        rotX(l1w[3*i], vx, vy, vz); rotY(l1w[3*i+1], vx, vy, vz); rotZ(l1w[3*i+2], vx, vy, vz);
        M[i][0][qb] = 1.f; M[i][1][qb] = vx; M[i][2][qb] = vz; M[i][3][qb] = vy;
    } else if (t < 96) {
        int q = t - 80;
        float sa, ca, sb, cb;
        __sincosf(l2w[3*q],   &sa, &ca);
        __sincosf(l2w[3*q+1], &sb, &cb);
        // O_q = U^dag Z U with U = RZ RY RX  ->  n = (-sin b, sin a cos b, cos a cos b)
        Nv[q][0] = -sb; Nv[q][1] = sa*cb; Nv[q][2] = ca*cb;
    }

    // ---- Clifford pullback via symplectic (X,Z) bitmasks — pure ALU, no LDC.
    // Pattern digits a_j (0=I,1=X,2=Y,3=Z) on qubits 0..3:
    const int a0 = t & 3, a1 = (t >> 2) & 3, a2 = (t >> 4) & 3, a3 = (t >> 6) & 3;
    unsigned X = 0u, Z = 0u;
    {
        // x-bit = (a ^ (a>>1)) & 1 ; z-bit = (a>>1) & 1
        X  = ((a0 ^ (a0 >> 1)) & 1);
        X |= ((a1 ^ (a1 >> 1)) & 1) << 1;
        X |= ((a2 ^ (a2 >> 1)) & 1) << 2;
        X |= ((a3 ^ (a3 >> 1)) & 1) << 3;
        Z  = ((a0 >> 1) & 1);
        Z |= ((a1 >> 1) & 1) << 1;
        Z |= ((a2 >> 1) & 1) << 2;
        Z |= ((a3 >> 1) & 1) << 3;
    }
    unsigned sign = 0u;
    // psi = C19...C0 |prod>  =>  conjugate by C19 first, C0 last.
    // CNOT(c,t):  x_t ^= x_c ; z_c ^= z_t ; sign ^= x_c & z_t & (1 ^ x_t ^ z_c)
    #pragma unroll
    for (int i = 19; i >= 0; --i) {
        const int c = i, tt = (i + 1) % 20;
        unsigned xc = (X >> c)  & 1u;
        unsigned zc = (Z >> c)  & 1u;
        unsigned xt = (X >> tt) & 1u;
        unsigned zt = (Z >> tt) & 1u;
        sign ^= xc & zt & (1u ^ xt ^ zc);
        X ^= xc << tt;
        Z ^= zt << c;
    }
    const float sgn = sign ? -1.f : 1.f;

    __syncthreads();

    // ---- <psi_qb | P | psi_qb> for all 4 blocks: one LDS.128 per qubit
    float v0 = sgn, v1 = sgn, v2 = sgn, v3 = sgn;
    #pragma unroll
    for (int i = 0; i < 20; ++i) {
        int p = (int)(((X >> i) & 1u) | (((Z >> i) & 1u) << 1));
        float4 f = *(const float4*)&M[i][p][0];
        v0 *= f.x; v1 *= f.y; v2 *= f.z; v3 *= f.w;
    }

    // ---- 7 expectations: [0..3] Efull[qb]; [4] e123; [5] e01; [6] e012
    float part[7] = {0,0,0,0,0,0,0};
    const bool f0 = a0 > 0, f1 = a1 > 0, f2 = a2 > 0, f3 = a3 > 0;
    if (f0 && f1 && f2 && f3) {
        part[0] = Nv[0][a0-1]  * Nv[1][a1-1]  * Nv[2][a2-1]  * Nv[3][a3-1]  * v0;
        part[1] = Nv[4][a0-1]  * Nv[5][a1-1]  * Nv[6][a2-1]  * Nv[7][a3-1]  * v1;
        part[2] = Nv[8][a0-1]  * Nv[9][a1-1]  * Nv[10][a2-1] * Nv[11][a3-1] * v2;
        part[3] = Nv[12][a0-1] * Nv[13][a1-1] * Nv[14][a2-1] * Nv[15][a3-1] * v3;
    }
    if (!f0 && f1 && f2 && f3)
        part[4] = Nv[1][a1-1] * Nv[2][a2-1] * Nv[3][a3-1] * v0;
    if (f0 && f1 && !f2 && !f3)
        part[5] = Nv[0][a0-1] * Nv[1][a1-1] * v0;
    if (f0 && f1 && f2 && !f3)
        part[6] = Nv[0][a0-1] * Nv[1][a1-1] * Nv[2][a2-1] * v0;

    #pragma unroll
    for (int k = 0; k < 7; ++k) {
        float r = wred(part[k]);
        if (lane == 0) acc[warp][k] = r;
    }
    __syncthreads();

    // Parallel final combine: threads 0..6 sum the 8 warp partials (fixed order).
    if (t < 7) {
        float v = 0.f;
        #pragma unroll
        for (int w = 0; w < 8; ++w) v += acc[w][t];
        Esh[t] = v;
    }
    __syncthreads();

    const float q0 = Esh[4] * Esh[1] * Esh[2] * Esh[3];  // e0
    const float q1 = Esh[5];                             // e1
    const float q2 = Esh[6];                             // e2
    const float q3 = Esh[0];                             // e3

    // ---- head: y = q @ W^T + b, then L2 normalize; 2 outputs per thread
    float y0 = b0 + q0*w0.x + q1*w0.y + q2*w0.z + q3*w0.w;
    float y1 = b1 + q0*w1.x + q1*w1.y + q2*w1.z + q3*w1.w;
    float ssum = wred(y0*y0 + y1*y1);
    if (lane == 0) nwarp[warp] = ssum;
    __syncthreads();

    float n = 0.f;
    #pragma unroll
    for (int w = 0; w < 8; ++w) n += nwarp[w];           // fixed order, all threads
    const float d = fmaxf(sqrtf(n), 1e-12f);
    const float r = 1.0f / d;
    out[(size_t)b*512 + k0] = y0 * r;
    out[(size_t)b*512 + k1] = y1 * r;
}

extern "C" void kernel_launch(void* const* d_in, const int* in_sizes, int n_in,
                              void* d_out, int out_size)
{
    // Map inputs by unique element counts:
    // x=1536, pos_weights=32, layer_1_weights=60, layer_2_weights=48,
    // head_w=2048, head_b=512
    const float *x = nullptr, *pw = nullptr, *l1 = nullptr,
                *l2 = nullptr, *hw = nullptr, *hb = nullptr;
    for (int i = 0; i < n_in; ++i) {
        const float* p = (const float*)d_in[i];
        switch (in_sizes[i]) {
            case 1536: x  = p; break;
            case 32:   pw = p; break;
            case 60:   l1 = p; break;
            case 48:   l2 = p; break;
            case 2048: hw = p; break;
            case 512:  hb = p; break;
            default: break;
        }
    }
    qie_kernel<<<8, 256>>>(x, pw, l1, l2, hw, hb, (float*)d_out);
}